// round 2
// baseline (speedup 1.0000x reference)
#include <cuda_runtime.h>

// ---------------------------------------------------------------------------
// ChannelProjection: per-sample LayerNorm over (C,H,W), 1x1-conv MLP
// (64 -> 128 -> SiLU -> 64) on channels [0,64), channel shuffle (groups=2),
// residual add.  z_0: (16,128,192,192) fp32.
//
// Strategy (round 0):
//   k1: deterministic two-stage per-sample sum / sumsq reduction
//   k2: finalize mu / rsigma per sample
//   k3: fused main kernel, 1 pixel/thread, all MACs as packed fma.rn.f32x2
//       (2 FMA/instr; ptxas never emits FFMA2 from C++, PTX-only),
//       weights staged in 64KB dynamic SMEM (w2 transposed + k-pair packed).
// ---------------------------------------------------------------------------

#define C_TOT   128
#define CC      64
#define HW      36864            // 192*192
#define NSAMP   16
#define CHW     (C_TOT * HW)     // 4718592
#define NPIX    (NSAMP * HW)     // 589824
#define RED_BLOCKS  64
#define RED_THREADS 256
#define MAIN_THREADS 128

__device__ float g_psum[NSAMP * RED_BLOCKS];
__device__ float g_psq [NSAMP * RED_BLOCKS];
__device__ float g_mu  [NSAMP];
__device__ float g_rs  [NSAMP];

typedef unsigned long long u64;

__device__ __forceinline__ u64 pack2(float x, float y) {
    u64 r;
    asm("mov.b64 %0, {%1, %2};" : "=l"(r) : "f"(x), "f"(y));
    return r;
}
__device__ __forceinline__ void unpack2(u64 v, float& x, float& y) {
    asm("mov.b64 {%0, %1}, %2;" : "=f"(x), "=f"(y) : "l"(v));
}
// packed dual FMA: d.lo = a.lo*b.lo + c.lo ; d.hi = a.hi*b.hi + c.hi
__device__ __forceinline__ u64 ffma2(u64 a, u64 b, u64 c) {
    u64 d;
    asm("fma.rn.f32x2 %0, %1, %2, %3;" : "=l"(d) : "l"(a), "l"(b), "l"(c));
    return d;
}

// ---------------- stage 1: per-sample partial sums (deterministic) ----------
__global__ void cp_stats_kernel(const float* __restrict__ z0) {
    const int b = blockIdx.y;
    const float4* z4 = (const float4*)(z0 + (size_t)b * CHW);
    const int n4 = CHW / 4;  // 1179648

    float s = 0.f, q = 0.f;
    for (int i = blockIdx.x * RED_THREADS + threadIdx.x; i < n4;
         i += RED_BLOCKS * RED_THREADS) {
        float4 v = z4[i];
        s += (v.x + v.y) + (v.z + v.w);
        q += (v.x * v.x + v.y * v.y) + (v.z * v.z + v.w * v.w);
    }
    // warp reduce
    #pragma unroll
    for (int off = 16; off; off >>= 1) {
        s += __shfl_down_sync(0xffffffffu, s, off);
        q += __shfl_down_sync(0xffffffffu, q, off);
    }
    __shared__ float ss[RED_THREADS / 32], sq[RED_THREADS / 32];
    const int w = threadIdx.x >> 5;
    if ((threadIdx.x & 31) == 0) { ss[w] = s; sq[w] = q; }
    __syncthreads();
    if (threadIdx.x == 0) {
        float S = 0.f, Q = 0.f;
        #pragma unroll
        for (int i = 0; i < RED_THREADS / 32; i++) { S += ss[i]; Q += sq[i]; }
        g_psum[b * RED_BLOCKS + blockIdx.x] = S;
        g_psq [b * RED_BLOCKS + blockIdx.x] = Q;
    }
}

// ---------------- stage 2: finalize mu / rsigma -----------------------------
__global__ void cp_finalize_kernel() {
    const int b = threadIdx.x;
    if (b < NSAMP) {
        float S = 0.f, Q = 0.f;
        for (int i = 0; i < RED_BLOCKS; i++) {
            S += g_psum[b * RED_BLOCKS + i];
            Q += g_psq [b * RED_BLOCKS + i];
        }
        const float inv_n = 1.f / (float)CHW;
        const float mu  = S * inv_n;
        const float var = Q * inv_n - mu * mu;
        g_mu[b] = mu;
        g_rs[b] = rsqrtf(var + 1e-5f);
    }
}

// ---------------- stage 3: fused norm + MLP + shuffle + residual ------------
// dyn smem: w1 (4096 u64) | w2T packed (4096 u64) | b1 (128 f) | b2 packed (32 u64)
#define SMEM_BYTES (4096 * 8 + 4096 * 8 + 128 * 4 + 32 * 8)   // 66304

__global__ void __launch_bounds__(MAIN_THREADS)
cp_main_kernel(const float* __restrict__ z0,
               const float* __restrict__ w1,
               const float* __restrict__ b1,
               const float* __restrict__ w2,
               const float* __restrict__ b2,
               float* __restrict__ out) {
    extern __shared__ u64 smem[];
    u64*   w1s = smem;                       // [128][32] pairs (raw copy of w1)
    u64*   w2s = smem + 4096;                // [o=128][j=32]: (w2[2j][o], w2[2j+1][o])
    float* b1s = (float*)(smem + 8192);      // 128
    u64*   b2s = (u64*)(b1s + 128);          // 32 pairs

    const int tid = threadIdx.x;

    // stage weights into shared
    const u64* w1g = (const u64*)w1;         // 8192 floats = 4096 u64, pairs already (c=2j,2j+1)
    for (int i = tid; i < 4096; i += MAIN_THREADS) w1s[i] = w1g[i];
    for (int idx = tid; idx < 4096; idx += MAIN_THREADS) {
        const int j = idx >> 7;              // k-pair index
        const int o = idx & 127;             // coalesced over o
        w2s[o * 32 + j] = pack2(w2[(2 * j) * C_TOT + o], w2[(2 * j + 1) * C_TOT + o]);
    }
    if (tid < 128) b1s[tid] = b1[tid];
    if (tid < 32)  b2s[tid] = ((const u64*)b2)[tid];
    __syncthreads();

    const int gid = blockIdx.x * MAIN_THREADS + tid;   // < NPIX (exact grid)
    const int b = gid / HW;
    const int p = gid - b * HW;
    const float* zb = z0 + (size_t)b * CHW;
    float*       ob = out + (size_t)b * CHW;
    const float mu = g_mu[b];
    const float rs = g_rs[b];

    // normalized z1 (channels 0..63), packed as 32 f32x2 pairs
    u64 zp[32], ap[32];
    #pragma unroll
    for (int j = 0; j < 32; j++) {
        const float a = (zb[(size_t)(2 * j)     * HW + p] - mu) * rs;
        const float c = (zb[(size_t)(2 * j + 1) * HW + p] - mu) * rs;
        zp[j] = pack2(a, c);
        ap[j] = b2s[j];                      // acc init = b2
    }

    // MLP: for each hidden unit o, h = <z1, w1[o]> + b1[o]; acc += silu(h) * w2T[o]
    #pragma unroll 2
    for (int o = 0; o < 128; o++) {
        const u64* wr = w1s + o * 32;
        u64 h0 = 0ull, h1 = 0ull;            // two chains to cut RAW latency
        #pragma unroll
        for (int j = 0; j < 32; j += 2) {
            h0 = ffma2(zp[j],     wr[j],     h0);
            h1 = ffma2(zp[j + 1], wr[j + 1], h1);
        }
        float ax, ay, bx, by;
        unpack2(h0, ax, ay); unpack2(h1, bx, by);
        const float h = (ax + ay) + (bx + by) + b1s[o];
        const float s = h * (1.f / (1.f + __expf(-h)));   // SiLU
        const u64 sv = pack2(s, s);
        const u64* wc = w2s + o * 32;
        #pragma unroll
        for (int j = 0; j < 32; j++) ap[j] = ffma2(sv, wc[j], ap[j]);
    }

    // channel shuffle (out[2i] = mlp[i], out[2i+1] = znorm[64+i]) + residual
    #pragma unroll
    for (int j = 0; j < 32; j++) {
        float a0, a1;
        unpack2(ap[j], a0, a1);
        const int k0 = 2 * j, k1 = 2 * j + 1;
        ob[(size_t)(2 * k0)     * HW + p] = a0 + zb[(size_t)(2 * k0)     * HW + p];
        ob[(size_t)(2 * k1)     * HW + p] = a1 + zb[(size_t)(2 * k1)     * HW + p];
        ob[(size_t)(2 * k0 + 1) * HW + p] =
            (zb[(size_t)(CC + k0) * HW + p] - mu) * rs + zb[(size_t)(2 * k0 + 1) * HW + p];
        ob[(size_t)(2 * k1 + 1) * HW + p] =
            (zb[(size_t)(CC + k1) * HW + p] - mu) * rs + zb[(size_t)(2 * k1 + 1) * HW + p];
    }
}

// ---------------------------------------------------------------------------
extern "C" void kernel_launch(void* const* d_in, const int* in_sizes, int n_in,
                              void* d_out, int out_size) {
    const float* z0 = (const float*)d_in[0];
    const float* w1 = (const float*)d_in[1];
    const float* b1 = (const float*)d_in[2];
    const float* w2 = (const float*)d_in[3];
    const float* b2 = (const float*)d_in[4];
    float* out = (float*)d_out;

    static bool attr_set = false;   // idempotent attribute set (runs on the
    if (!attr_set) {                // un-captured correctness call first)
        cudaFuncSetAttribute(cp_main_kernel,
                             cudaFuncAttributeMaxDynamicSharedMemorySize,
                             SMEM_BYTES);
        attr_set = true;
    }

    cp_stats_kernel<<<dim3(RED_BLOCKS, NSAMP), RED_THREADS>>>(z0);
    cp_finalize_kernel<<<1, 32>>>();
    cp_main_kernel<<<NPIX / MAIN_THREADS, MAIN_THREADS, SMEM_BYTES>>>(
        z0, w1, b1, w2, b2, out);
}